// round 16
// baseline (speedup 1.0000x reference)
#include <cuda_runtime.h>
#include <cuda_bf16.h>
#include <stdint.h>
#include <math.h>

#define N_NODES 100000
#define N_CLASS 10
#define HIDDEN 128
#define BN_EPS 1e-5

// ---------------- scratch (device globals; no runtime allocation) ----------------
__device__ float  g_buf1[(size_t)N_NODES * HIDDEN];   // z1 / z3
__device__ float  g_buf2[(size_t)N_NODES * HIDDEN];   // z2 / z4
__device__ float  g_agg2[(size_t)N_NODES * HIDDEN];   // layer-2 aggregation
__device__ float  g_agg1[(size_t)N_NODES * N_CLASS];  // layer-1 aggregation
__device__ double g_bnsum[4 * HIDDEN];
__device__ double g_bnsq[4 * HIDDEN];
__device__ float  g_scale[4 * HIDDEN];
__device__ float  g_shift[4 * HIDDEN];

// ---------------- helpers ----------------
__device__ __forceinline__ void red_add_v4(float* addr, float4 v) {
    asm volatile("red.global.add.v4.f32 [%0], {%1,%2,%3,%4};"
                 :: "l"(addr), "f"(v.x), "f"(v.y), "f"(v.z), "f"(v.w) : "memory");
}
__device__ __forceinline__ void red_add_v2(float* addr, float2 v) {
    asm volatile("red.global.add.v2.f32 [%0], {%1,%2};"
                 :: "l"(addr), "f"(v.x), "f"(v.y) : "memory");
}
__device__ __forceinline__ float to_tf32(float x) {
    uint32_t u;
    asm("cvt.rna.tf32.f32 %0, %1;" : "=r"(u) : "f"(x));
    return __uint_as_float(u);
}
__device__ __forceinline__ void mma_tf32(float& d0, float& d1, float& d2, float& d3,
                                         uint32_t a0, uint32_t a1, uint32_t a2, uint32_t a3,
                                         uint32_t b0, uint32_t b1) {
    asm volatile("mma.sync.aligned.m16n8k8.row.col.f32.tf32.tf32.f32 "
                 "{%0,%1,%2,%3}, {%4,%5,%6,%7}, {%8,%9}, {%0,%1,%2,%3};"
                 : "+f"(d0), "+f"(d1), "+f"(d2), "+f"(d3)
                 : "r"(a0), "r"(a1), "r"(a2), "r"(a3), "r"(b0), "r"(b1));
}

// ---------------- layer-1 scatter: agg1[dst] += x[src], D=10 ----------------
__global__ void scatter1_kernel(const float* __restrict__ x,
                                const int* __restrict__ src,
                                const int* __restrict__ dst,
                                float* __restrict__ agg1, int E) {
    int e = blockIdx.x * blockDim.x + threadIdx.x;
    if (e >= E) return;
    int s = __ldg(&src[e]), d = __ldg(&dst[e]);
    const float2* xr = (const float2*)(x + (size_t)s * N_CLASS);
    float* ar = agg1 + (size_t)d * N_CLASS;
#pragma unroll
    for (int i = 0; i < 5; i++) {
        float2 v = __ldg(&xr[i]);
        red_add_v2(ar + 2 * i, v);
    }
}

// ---------------- GEMM1: z1 = (x + agg1) @ w11 + b11, K=10; accumulate BN stats ----------------
__global__ void gemm1_kernel(const float* __restrict__ x,
                             const float* __restrict__ agg1,
                             const float* __restrict__ w11,
                             const float* __restrict__ b11,
                             float* __restrict__ z1,
                             double* __restrict__ sumOut,
                             double* __restrict__ sqOut, int N) {
    __shared__ float ws[N_CLASS * HIDDEN];
    __shared__ float xs[8][N_CLASS];
    __shared__ float ssum[HIDDEN], ssq[HIDDEN];
    int tx = threadIdx.x, ty = threadIdx.y;
    int tid = ty * HIDDEN + tx;
    for (int i = tid; i < N_CLASS * HIDDEN; i += HIDDEN * 8) ws[i] = w11[i];
    if (tid < HIDDEN) { ssum[tid] = 0.f; ssq[tid] = 0.f; }
    int row = blockIdx.x * 8 + ty;
    if (tx < N_CLASS && row < N)
        xs[ty][tx] = x[(size_t)row * N_CLASS + tx] + agg1[(size_t)row * N_CLASS + tx];
    __syncthreads();
    if (row < N) {
        float z = __ldg(&b11[tx]);
#pragma unroll
        for (int k = 0; k < N_CLASS; k++) z += xs[ty][k] * ws[k * HIDDEN + tx];
        z1[(size_t)row * HIDDEN + tx] = z;
        atomicAdd(&ssum[tx], z);
        atomicAdd(&ssq[tx], z * z);
    }
    __syncthreads();
    if (tid < HIDDEN) {
        atomicAdd(&sumOut[tid], (double)ssum[tid]);
        atomicAdd(&sqOut[tid], (double)ssq[tid]);
    }
}

// ---------------- BN finalize ----------------
__global__ void bn_finalize(const double* __restrict__ sum,
                            const double* __restrict__ sq,
                            const float* __restrict__ g,
                            const float* __restrict__ t,
                            float* __restrict__ scale,
                            float* __restrict__ shift, double invN) {
    int j = threadIdx.x;
    double m = sum[j] * invN;
    double v = sq[j] * invN - m * m;
    if (v < 0.0) v = 0.0;
    double inv = (double)g[j] / sqrt(v + (double)BN_EPS);
    scale[j] = (float)inv;
    shift[j] = (float)((double)t[j] - m * inv);
}

// ---------------- main GEMM (TF32 tensor cores): Zout = act(A) @ W + bias + BN-stat epilogue ----
// MODE 0: act(z) = relu(scale*z + shift)
// MODE 1: act(z) = relu(scale*z + shift) + agg[row]
// CTA 128x128, 8 warps, warp tile 64x32 (m16n8k8, 4mt x 4nt).
// Fragment-PAIR smem layouts (float2 = (k, k+4) pair) -> all frag reads are LDS.64:
//   As2[r * APF2 + ks*4 + t]          = { A[r][k0+t],      A[r][k0+t+4] }      (k local to chunk)
//   Bs2[(kb*4 + t) * BPF2 + n]        = { W[kb*8+t][n],    W[kb*8+t+4][n] }    (kb global)
// Bank check (16-lane phase, float2 units): A: (4g+t)%16 distinct; B: (4t+g)%16 distinct.
// tf32 m16n8k8 maps: A a0=(g,t) a1=(g+8,t) a2=(g,t+4) a3=(g+8,t+4); B b0=(t,n+g) b1=(t+4,n+g);
//                    D d0=(g,2t) d1=(g,2t+1) d2=(g+8,2t) d3=(g+8,2t+1)
#define MTILE 128
#define KC 64
#define APF2 36        // A float2 row pitch (36 % 16 == 4)
#define BPF2 132       // B float2 row pitch (132 % 16 == 4)
#define BS2_SIZE (64 * BPF2)            // 64 (kb,t)-rows
#define AS2_SIZE (MTILE * APF2)
template <int MODE>
__global__ __launch_bounds__(256, 2) void gemmB(
    const float* __restrict__ Ain, const float* __restrict__ agg,
    const float* __restrict__ W, const float* __restrict__ bias,
    const float* __restrict__ scale, const float* __restrict__ shift,
    float* __restrict__ Zout, double* __restrict__ sumOut,
    double* __restrict__ sqOut, int N) {
    extern __shared__ float smemf[];
    float2* Bs2 = (float2*)smemf;                    // [64][132] float2
    float2* As2 = Bs2 + BS2_SIZE;                    // [128][36] float2
    float* ssum = smemf + 2 * (BS2_SIZE + AS2_SIZE); // [128]
    float* ssq = ssum + HIDDEN;                      // [128]
    __shared__ float sc[HIDDEN], sh[HIDDEN];

    int tid = threadIdx.x;
    int row0 = blockIdx.x * MTILE;
    if (tid < HIDDEN) {
        ssum[tid] = 0.f; ssq[tid] = 0.f;
        sc[tid] = scale[tid]; sh[tid] = shift[tid];
    }
    // load full B (128x128 weight) -> tf32, fragment-pair layout
    float* Bsf = (float*)Bs2;
    for (int i = tid; i < HIDDEN * (HIDDEN / 4); i += 256) {
        int k = i >> 5, c4 = (i & 31) * 4;
        float4 w = *(const float4*)&W[k * HIDDEN + c4];
        int kb = k >> 3, rm = k & 7, t = rm & 3, j = rm >> 2;
        int rowbase = (kb * 4 + t) * BPF2;
        Bsf[(rowbase + c4 + 0) * 2 + j] = to_tf32(w.x);
        Bsf[(rowbase + c4 + 1) * 2 + j] = to_tf32(w.y);
        Bsf[(rowbase + c4 + 2) * 2 + j] = to_tf32(w.z);
        Bsf[(rowbase + c4 + 3) * 2 + j] = to_tf32(w.w);
    }

    int lane = tid & 31, wid = tid >> 5;
    int wm = wid & 1, wn = wid >> 1;          // warp tile: rows wm*64, cols wn*32
    int g = lane >> 2, t = lane & 3;          // groupID, thread-in-group

    float d[4][4][4];                          // [m-tile][n-tile][4 accum]
#pragma unroll
    for (int mt = 0; mt < 4; mt++)
#pragma unroll
        for (int nt = 0; nt < 4; nt++)
#pragma unroll
            for (int q = 0; q < 4; q++) d[mt][nt][q] = 0.f;

    float* Asf = (float*)As2;
    for (int kc = 0; kc < HIDDEN; kc += KC) {
        __syncthreads();   // As reuse guard; first pass orders Bs/sc/sh before reads
        // fill A chunk: 128 rows x 64 k, fragment-pair layout
        for (int i = tid; i < MTILE * (KC / 4); i += 256) {
            int r = i / (KC / 4), k4 = (i % (KC / 4)) * 4;
            int gk = kc + k4;
            int gr = row0 + r;
            float4 v = make_float4(0.f, 0.f, 0.f, 0.f);
            if (gr < N) {
                float4 z = *(const float4*)&Ain[(size_t)gr * HIDDEN + gk];
                v.x = fmaxf(0.f, sc[gk + 0] * z.x + sh[gk + 0]);
                v.y = fmaxf(0.f, sc[gk + 1] * z.y + sh[gk + 1]);
                v.z = fmaxf(0.f, sc[gk + 2] * z.z + sh[gk + 2]);
                v.w = fmaxf(0.f, sc[gk + 3] * z.w + sh[gk + 3]);
                if (MODE == 1) {
                    float4 a = *(const float4*)&agg[(size_t)gr * HIDDEN + gk];
                    v.x += a.x; v.y += a.y; v.z += a.z; v.w += a.w;
                }
                v.x = to_tf32(v.x); v.y = to_tf32(v.y); v.z = to_tf32(v.z); v.w = to_tf32(v.w);
            }
            // local k = k4..k4+3 (all same j since k4 % 4 == 0 and j = (k%8)/4)
            int kb = k4 >> 3, rm = k4 & 7, j = rm >> 2;   // t runs 0..3 over the 4 elems
            int base = r * APF2 + kb * 4;
            Asf[(base + 0) * 2 + j] = v.x;
            Asf[(base + 1) * 2 + j] = v.y;
            Asf[(base + 2) * 2 + j] = v.z;
            Asf[(base + 3) * 2 + j] = v.w;
        }
        __syncthreads();

#pragma unroll
        for (int ks = 0; ks < KC / 8; ks++) {
            int kbg = (kc >> 3) + ks;     // global kb for B
            uint32_t af[4][4];
#pragma unroll
            for (int mt = 0; mt < 4; mt++) {
                int m = wm * 64 + mt * 16;
                float2 aA = As2[(m + g) * APF2 + ks * 4 + t];
                float2 aB = As2[(m + g + 8) * APF2 + ks * 4 + t];
                af[mt][0] = __float_as_uint(aA.x);   // (g, t)
                af[mt][1] = __float_as_uint(aB.x);   // (g+8, t)
                af[mt][2] = __float_as_uint(aA.y);   // (g, t+4)
                af[mt][3] = __float_as_uint(aB.y);   // (g+8, t+4)
            }
            uint32_t bf[4][2];
#pragma unroll
            for (int nt = 0; nt < 4; nt++) {
                int n = wn * 32 + nt * 8;
                float2 bb = Bs2[(kbg * 4 + t) * BPF2 + n + g];
                bf[nt][0] = __float_as_uint(bb.x);   // (t,   n+g)
                bf[nt][1] = __float_as_uint(bb.y);   // (t+4, n+g)
            }
#pragma unroll
            for (int mt = 0; mt < 4; mt++)
#pragma unroll
                for (int nt = 0; nt < 4; nt++)
                    mma_tf32(d[mt][nt][0], d[mt][nt][1], d[mt][nt][2], d[mt][nt][3],
                             af[mt][0], af[mt][1], af[mt][2], af[mt][3],
                             bf[nt][0], bf[nt][1]);
        }
    }

    // epilogue: bias, store, column stats
    // d0 -> (g, 2t), d1 -> (g, 2t+1), d2 -> (g+8, 2t), d3 -> (g+8, 2t+1)
#pragma unroll
    for (int nt = 0; nt < 4; nt++) {
        int c = wn * 32 + nt * 8 + 2 * t;
        float b0 = __ldg(&bias[c]), b1 = __ldg(&bias[c + 1]);
        float ps0 = 0.f, ps1 = 0.f, pq0 = 0.f, pq1 = 0.f;
#pragma unroll
        for (int mt = 0; mt < 4; mt++) {
            int gr0 = row0 + wm * 64 + mt * 16 + g;
            int gr1 = gr0 + 8;
            if (gr0 < N) {
                float z0 = d[mt][nt][0] + b0;
                float z1 = d[mt][nt][1] + b1;
                ps0 += z0; pq0 += z0 * z0;
                ps1 += z1; pq1 += z1 * z1;
                *(float2*)&Zout[(size_t)gr0 * HIDDEN + c] = make_float2(z0, z1);
            }
            if (gr1 < N) {
                float z2 = d[mt][nt][2] + b0;
                float z3 = d[mt][nt][3] + b1;
                ps0 += z2; pq0 += z2 * z2;
                ps1 += z3; pq1 += z3 * z3;
                *(float2*)&Zout[(size_t)gr1 * HIDDEN + c] = make_float2(z2, z3);
            }
        }
        atomicAdd(&ssum[c], ps0);
        atomicAdd(&ssq[c], pq0);
        atomicAdd(&ssum[c + 1], ps1);
        atomicAdd(&ssq[c + 1], pq1);
    }
    __syncthreads();
    if (tid < HIDDEN) {
        atomicAdd(&sumOut[tid], (double)ssum[tid]);
        atomicAdd(&sqOut[tid], (double)ssq[tid]);
    }
}

// ---------------- layer-2 scatter: agg2[dst] += relu(bn(z2))[src], warp/edge, D=128 ----------
__global__ void scatter2_kernel(const float* __restrict__ z2,
                                const float* __restrict__ scale,
                                const float* __restrict__ shift,
                                const int* __restrict__ src,
                                const int* __restrict__ dst,
                                float* __restrict__ agg2, int E) {
    __shared__ float sc[HIDDEN], sh[HIDDEN];
    int tid = threadIdx.x;
    if (tid < HIDDEN) { sc[tid] = scale[tid]; sh[tid] = shift[tid]; }
    __syncthreads();
    int warp = tid >> 5, lane = tid & 31;
    int e = blockIdx.x * 8 + warp;
    if (e >= E) return;
    int s = __ldg(&src[e]);
    int d = __ldg(&dst[e]);
    int o = lane * 4;
    float4 z = *(const float4*)&z2[(size_t)s * HIDDEN + o];
    float4 v;
    v.x = fmaxf(0.f, sc[o + 0] * z.x + sh[o + 0]);
    v.y = fmaxf(0.f, sc[o + 1] * z.y + sh[o + 1]);
    v.z = fmaxf(0.f, sc[o + 2] * z.z + sh[o + 2]);
    v.w = fmaxf(0.f, sc[o + 3] * z.w + sh[o + 3]);
    red_add_v4(&agg2[(size_t)d * HIDDEN + o], v);
}

// ---------------- final: logits = relu(bn(z4)) @ wf + bf -> log_softmax, warp/row ----------
__global__ void final_kernel(const float* __restrict__ z4,
                             const float* __restrict__ scale,
                             const float* __restrict__ shift,
                             const float* __restrict__ wf,
                             const float* __restrict__ bf,
                             float* __restrict__ out, int N) {
    __shared__ float wfs[HIDDEN * N_CLASS];
    __shared__ float sc[HIDDEN], sh[HIDDEN];
    int tid = threadIdx.x;
    for (int i = tid; i < HIDDEN * N_CLASS; i += 256) wfs[i] = wf[i];
    if (tid < HIDDEN) { sc[tid] = scale[tid]; sh[tid] = shift[tid]; }
    __syncthreads();
    int warp = tid >> 5, lane = tid & 31;
    int n = blockIdx.x * 8 + warp;
    if (n >= N) return;
    int o = lane * 4;
    float4 z = *(const float4*)&z4[(size_t)n * HIDDEN + o];
    float y[4];
    y[0] = fmaxf(0.f, sc[o + 0] * z.x + sh[o + 0]);
    y[1] = fmaxf(0.f, sc[o + 1] * z.y + sh[o + 1]);
    y[2] = fmaxf(0.f, sc[o + 2] * z.z + sh[o + 2]);
    y[3] = fmaxf(0.f, sc[o + 3] * z.w + sh[o + 3]);
    float acc[N_CLASS];
#pragma unroll
    for (int j = 0; j < N_CLASS; j++) acc[j] = 0.f;
#pragma unroll
    for (int i = 0; i < 4; i++) {
        const float* wr = &wfs[(o + i) * N_CLASS];
#pragma unroll
        for (int j = 0; j < N_CLASS; j++) acc[j] = fmaf(y[i], wr[j], acc[j]);
    }
#pragma unroll
    for (int off = 16; off > 0; off >>= 1)
#pragma unroll
        for (int j = 0; j < N_CLASS; j++)
            acc[j] += __shfl_xor_sync(0xFFFFFFFFu, acc[j], off);
    if (lane == 0) {
        float l[N_CLASS];
        float m = -1e30f;
#pragma unroll
        for (int j = 0; j < N_CLASS; j++) {
            l[j] = acc[j] + __ldg(&bf[j]);
            m = fmaxf(m, l[j]);
        }
        float s = 0.f;
#pragma unroll
        for (int j = 0; j < N_CLASS; j++) s += __expf(l[j] - m);
        float lg = m + logf(s);
#pragma unroll
        for (int j = 0; j < N_CLASS; j++) out[(size_t)n * N_CLASS + j] = l[j] - lg;
    }
}

// ---------------- host launch ----------------
extern "C" void kernel_launch(void* const* d_in, const int* in_sizes, int n_in,
                              void* d_out, int out_size) {
    const float* x   = (const float*)d_in[0];
    const float* w11 = (const float*)d_in[2];
    const float* b11 = (const float*)d_in[3];
    const float* g11 = (const float*)d_in[4];
    const float* t11 = (const float*)d_in[5];
    const float* w12 = (const float*)d_in[6];
    const float* b12 = (const float*)d_in[7];
    const float* g12 = (const float*)d_in[8];
    const float* t12 = (const float*)d_in[9];
    const float* w21 = (const float*)d_in[10];
    const float* b21 = (const float*)d_in[11];
    const float* g21 = (const float*)d_in[12];
    const float* t21 = (const float*)d_in[13];
    const float* w22 = (const float*)d_in[14];
    const float* b22 = (const float*)d_in[15];
    const float* g22 = (const float*)d_in[16];
    const float* t22 = (const float*)d_in[17];
    const float* wf  = (const float*)d_in[18];
    const float* bf  = (const float*)d_in[19];
    const int*   ei  = (const int*)d_in[20];   // int32 on device (harness dtype set)

    int N = in_sizes[0] / N_CLASS;       // 100000
    int E = in_sizes[20] / 2;            // 1600000
    const int* src = ei;
    const int* dst = ei + E;

    float *agg1, *agg2, *buf1, *buf2, *scale, *shift;
    double *bnsum, *bnsq;
    cudaGetSymbolAddress((void**)&agg1, g_agg1);
    cudaGetSymbolAddress((void**)&agg2, g_agg2);
    cudaGetSymbolAddress((void**)&buf1, g_buf1);
    cudaGetSymbolAddress((void**)&buf2, g_buf2);
    cudaGetSymbolAddress((void**)&scale, g_scale);
    cudaGetSymbolAddress((void**)&shift, g_shift);
    cudaGetSymbolAddress((void**)&bnsum, g_bnsum);
    cudaGetSymbolAddress((void**)&bnsq, g_bnsq);

    const size_t SMEM_GEMM = (size_t)(2 * (BS2_SIZE + AS2_SIZE) + 2 * HIDDEN) * sizeof(float);
    cudaFuncSetAttribute(gemmB<0>, cudaFuncAttributeMaxDynamicSharedMemorySize, (int)SMEM_GEMM);
    cudaFuncSetAttribute(gemmB<1>, cudaFuncAttributeMaxDynamicSharedMemorySize, (int)SMEM_GEMM);

    cudaMemsetAsync(agg1, 0, (size_t)N * N_CLASS * sizeof(float), 0);
    cudaMemsetAsync(agg2, 0, (size_t)N * HIDDEN * sizeof(float), 0);
    cudaMemsetAsync(bnsum, 0, 4 * HIDDEN * sizeof(double), 0);
    cudaMemsetAsync(bnsq, 0, 4 * HIDDEN * sizeof(double), 0);

    double invN = 1.0 / (double)N;
    int gBlocks = (N + MTILE - 1) / MTILE;

    // layer 1
    scatter1_kernel<<<(E + 255) / 256, 256>>>(x, src, dst, agg1, E);
    gemm1_kernel<<<(N + 7) / 8, dim3(HIDDEN, 8)>>>(x, agg1, w11, b11, buf1,
                                                   bnsum + 0 * HIDDEN, bnsq + 0 * HIDDEN, N);
    bn_finalize<<<1, HIDDEN>>>(bnsum + 0 * HIDDEN, bnsq + 0 * HIDDEN, g11, t11,
                               scale + 0 * HIDDEN, shift + 0 * HIDDEN, invN);
    gemmB<0><<<gBlocks, 256, SMEM_GEMM>>>(buf1, nullptr, w12, b12,
                                          scale + 0 * HIDDEN, shift + 0 * HIDDEN,
                                          buf2, bnsum + 1 * HIDDEN, bnsq + 1 * HIDDEN, N);
    bn_finalize<<<1, HIDDEN>>>(bnsum + 1 * HIDDEN, bnsq + 1 * HIDDEN, g12, t12,
                               scale + 1 * HIDDEN, shift + 1 * HIDDEN, invN);

    // layer 2 (h_out1 = relu(bn1(z2)) recomputed on the fly; never materialized)
    scatter2_kernel<<<(E + 7) / 8, 256>>>(buf2, scale + 1 * HIDDEN, shift + 1 * HIDDEN,
                                          src, dst, agg2, E);
    gemmB<1><<<gBlocks, 256, SMEM_GEMM>>>(buf2, agg2, w21, b21,
                                          scale + 1 * HIDDEN, shift + 1 * HIDDEN,
                                          buf1, bnsum + 2 * HIDDEN, bnsq + 2 * HIDDEN, N);
    bn_finalize<<<1, HIDDEN>>>(bnsum + 2 * HIDDEN, bnsq + 2 * HIDDEN, g21, t21,
                               scale + 2 * HIDDEN, shift + 2 * HIDDEN, invN);
    gemmB<0><<<gBlocks, 256, SMEM_GEMM>>>(buf1, nullptr, w22, b22,
                                          scale + 2 * HIDDEN, shift + 2 * HIDDEN,
                                          buf2, bnsum + 3 * HIDDEN, bnsq + 3 * HIDDEN, N);
    bn_finalize<<<1, HIDDEN>>>(bnsum + 3 * HIDDEN, bnsq + 3 * HIDDEN, g22, t22,
                               scale + 3 * HIDDEN, shift + 3 * HIDDEN, invN);

    // readout
    final_kernel<<<(N + 7) / 8, 256>>>(buf2, scale + 3 * HIDDEN, shift + 3 * HIDDEN,
                                       wf, bf, (float*)d_out, N);
}

// round 17
// speedup vs baseline: 1.3969x; 1.3969x over previous
#include <cuda_runtime.h>
#include <cuda_bf16.h>
#include <stdint.h>
#include <math.h>

#define N_NODES 100000
#define N_CLASS 10
#define HIDDEN 128
#define BN_EPS 1e-5

// ---------------- scratch (device globals; no runtime allocation) ----------------
__device__ float  g_buf1[(size_t)N_NODES * HIDDEN];   // z1 / z3
__device__ float  g_buf2[(size_t)N_NODES * HIDDEN];   // z2 / z4
__device__ float  g_agg2[(size_t)N_NODES * HIDDEN];   // layer-2 aggregation
__device__ float  g_agg1[(size_t)N_NODES * N_CLASS];  // layer-1 aggregation
__device__ double g_bnsum[4 * HIDDEN];
__device__ double g_bnsq[4 * HIDDEN];
__device__ float  g_scale[4 * HIDDEN];
__device__ float  g_shift[4 * HIDDEN];

// ---------------- helpers ----------------
__device__ __forceinline__ void red_add_v4(float* addr, float4 v) {
    asm volatile("red.global.add.v4.f32 [%0], {%1,%2,%3,%4};"
                 :: "l"(addr), "f"(v.x), "f"(v.y), "f"(v.z), "f"(v.w) : "memory");
}
__device__ __forceinline__ void red_add_v2(float* addr, float2 v) {
    asm volatile("red.global.add.v2.f32 [%0], {%1,%2};"
                 :: "l"(addr), "f"(v.x), "f"(v.y) : "memory");
}
__device__ __forceinline__ float to_tf32(float x) {
    uint32_t u;
    asm("cvt.rna.tf32.f32 %0, %1;" : "=r"(u) : "f"(x));
    return __uint_as_float(u);
}
__device__ __forceinline__ void mma_tf32(float& d0, float& d1, float& d2, float& d3,
                                         uint32_t a0, uint32_t a1, uint32_t a2, uint32_t a3,
                                         uint32_t b0, uint32_t b1) {
    asm volatile("mma.sync.aligned.m16n8k8.row.col.f32.tf32.tf32.f32 "
                 "{%0,%1,%2,%3}, {%4,%5,%6,%7}, {%8,%9}, {%0,%1,%2,%3};"
                 : "+f"(d0), "+f"(d1), "+f"(d2), "+f"(d3)
                 : "r"(a0), "r"(a1), "r"(a2), "r"(a3), "r"(b0), "r"(b1));
}

// ---------------- layer-1 scatter: agg1[dst] += x[src], D=10 ----------------
__global__ void scatter1_kernel(const float* __restrict__ x,
                                const int* __restrict__ src,
                                const int* __restrict__ dst,
                                float* __restrict__ agg1, int E) {
    int e = blockIdx.x * blockDim.x + threadIdx.x;
    if (e >= E) return;
    int s = __ldg(&src[e]), d = __ldg(&dst[e]);
    const float2* xr = (const float2*)(x + (size_t)s * N_CLASS);
    float* ar = agg1 + (size_t)d * N_CLASS;
#pragma unroll
    for (int i = 0; i < 5; i++) {
        float2 v = __ldg(&xr[i]);
        red_add_v2(ar + 2 * i, v);
    }
}

// ---------------- GEMM1: z1 = (x + agg1) @ w11 + b11, K=10; accumulate BN stats ----------------
__global__ void gemm1_kernel(const float* __restrict__ x,
                             const float* __restrict__ agg1,
                             const float* __restrict__ w11,
                             const float* __restrict__ b11,
                             float* __restrict__ z1,
                             double* __restrict__ sumOut,
                             double* __restrict__ sqOut, int N) {
    __shared__ float ws[N_CLASS * HIDDEN];
    __shared__ float xs[8][N_CLASS];
    __shared__ float ssum[HIDDEN], ssq[HIDDEN];
    int tx = threadIdx.x, ty = threadIdx.y;
    int tid = ty * HIDDEN + tx;
    for (int i = tid; i < N_CLASS * HIDDEN; i += HIDDEN * 8) ws[i] = w11[i];
    if (tid < HIDDEN) { ssum[tid] = 0.f; ssq[tid] = 0.f; }
    int row = blockIdx.x * 8 + ty;
    if (tx < N_CLASS && row < N)
        xs[ty][tx] = x[(size_t)row * N_CLASS + tx] + agg1[(size_t)row * N_CLASS + tx];
    __syncthreads();
    if (row < N) {
        float z = __ldg(&b11[tx]);
#pragma unroll
        for (int k = 0; k < N_CLASS; k++) z += xs[ty][k] * ws[k * HIDDEN + tx];
        z1[(size_t)row * HIDDEN + tx] = z;
        atomicAdd(&ssum[tx], z);
        atomicAdd(&ssq[tx], z * z);
    }
    __syncthreads();
    if (tid < HIDDEN) {
        atomicAdd(&sumOut[tid], (double)ssum[tid]);
        atomicAdd(&sqOut[tid], (double)ssq[tid]);
    }
}

// ---------------- BN finalize ----------------
__global__ void bn_finalize(const double* __restrict__ sum,
                            const double* __restrict__ sq,
                            const float* __restrict__ g,
                            const float* __restrict__ t,
                            float* __restrict__ scale,
                            float* __restrict__ shift, double invN) {
    int j = threadIdx.x;
    double m = sum[j] * invN;
    double v = sq[j] * invN - m * m;
    if (v < 0.0) v = 0.0;
    double inv = (double)g[j] / sqrt(v + (double)BN_EPS);
    scale[j] = (float)inv;
    shift[j] = (float)((double)t[j] - m * inv);
}

// ---------------- main GEMM (TF32 tensor cores): Zout = act(A) @ W + bias + BN-stat epilogue ----
// MODE 0: act(z) = relu(scale*z + shift)
// MODE 1: act(z) = relu(scale*z + shift) + agg[row]
// Split-N: CTA computes 128 rows x 64 cols (blockIdx.y selects col half) -> ~70KB smem,
// 3 CTAs/SM. 8 warps, warp tile 64x16 (m16n8k8, 4 m-tiles x 2 n-tiles).
// A streamed in two 64-wide K chunks (pitch 68), B resident full-K 64 cols (pitch 68).
// tf32 m16n8k8 maps: A a0=(g,t) a1=(g+8,t) a2=(g,t+4) a3=(g+8,t+4); B b0=(t,n+g) b1=(t+4,n+g);
//                    D d0=(g,2t) d1=(g,2t+1) d2=(g+8,2t) d3=(g+8,2t+1)
#define MTILE 128
#define NTILE 64
#define KC 64
#define APD 68     // A chunk pitch (A-read bank 4g+t  -> conflict-free; unchanged from R15)
#define BPD 68     // B pitch      (B-read bank 4t+g  -> conflict-free)
template <int MODE>
__global__ __launch_bounds__(256, 3) void gemmB(
    const float* __restrict__ Ain, const float* __restrict__ agg,
    const float* __restrict__ W, const float* __restrict__ bias,
    const float* __restrict__ scale, const float* __restrict__ shift,
    float* __restrict__ Zout, double* __restrict__ sumOut,
    double* __restrict__ sqOut, int N) {
    extern __shared__ float smem[];
    float* Bs = smem;                        // [128][68]  tf32 (64 cols of W)
    float* As = Bs + HIDDEN * BPD;           // [128][68]  one 64-wide K chunk
    float* ssum = As + MTILE * APD;          // [64]
    float* ssq = ssum + NTILE;               // [64]
    __shared__ float sc[HIDDEN], sh[HIDDEN];

    int tid = threadIdx.x;
    int row0 = blockIdx.x * MTILE;
    int col0 = blockIdx.y * NTILE;
    if (tid < NTILE) { ssum[tid] = 0.f; ssq[tid] = 0.f; }
    if (tid < HIDDEN) { sc[tid] = scale[tid]; sh[tid] = shift[tid]; }
    // load B tile (128 k x 64 cols of weight) -> tf32
    for (int i = tid; i < HIDDEN * (NTILE / 4); i += 256) {
        int k = i / (NTILE / 4), c4 = (i % (NTILE / 4)) * 4;
        float4 w = *(const float4*)&W[k * HIDDEN + col0 + c4];
        w.x = to_tf32(w.x); w.y = to_tf32(w.y); w.z = to_tf32(w.z); w.w = to_tf32(w.w);
        *(float4*)&Bs[k * BPD + c4] = w;
    }

    int lane = tid & 31, wid = tid >> 5;
    int wm = wid & 1, wn = wid >> 1;          // warp tile: rows wm*64, cols wn*16
    int g = lane >> 2, t = lane & 3;          // groupID, thread-in-group

    float d[4][2][4];                          // [m-tile][n-tile][4 accum]
#pragma unroll
    for (int mt = 0; mt < 4; mt++)
#pragma unroll
        for (int nt = 0; nt < 2; nt++)
#pragma unroll
            for (int q = 0; q < 4; q++) d[mt][nt][q] = 0.f;

    for (int kc = 0; kc < HIDDEN; kc += KC) {
        __syncthreads();   // As reuse guard; first pass orders Bs/sc/sh writes before reads
        // fill A chunk: 128 rows x 64 k  (BN+relu(+agg) transform, tf32 round)
        for (int i = tid; i < MTILE * (KC / 4); i += 256) {
            int r = i / (KC / 4), k4 = (i % (KC / 4)) * 4;
            int gk = kc + k4;
            int gr = row0 + r;
            float4 v = make_float4(0.f, 0.f, 0.f, 0.f);
            if (gr < N) {
                float4 z = *(const float4*)&Ain[(size_t)gr * HIDDEN + gk];
                v.x = fmaxf(0.f, sc[gk + 0] * z.x + sh[gk + 0]);
                v.y = fmaxf(0.f, sc[gk + 1] * z.y + sh[gk + 1]);
                v.z = fmaxf(0.f, sc[gk + 2] * z.z + sh[gk + 2]);
                v.w = fmaxf(0.f, sc[gk + 3] * z.w + sh[gk + 3]);
                if (MODE == 1) {
                    float4 a = *(const float4*)&agg[(size_t)gr * HIDDEN + gk];
                    v.x += a.x; v.y += a.y; v.z += a.z; v.w += a.w;
                }
                v.x = to_tf32(v.x); v.y = to_tf32(v.y); v.z = to_tf32(v.z); v.w = to_tf32(v.w);
            }
            *(float4*)&As[r * APD + k4] = v;
        }
        __syncthreads();

#pragma unroll
        for (int ks = 0; ks < KC / 8; ks++) {
            int k0 = ks * 8;          // k local to chunk (As)
            int kg = kc + k0;         // global k (Bs)
            uint32_t af[4][4];
#pragma unroll
            for (int mt = 0; mt < 4; mt++) {
                int m = wm * 64 + mt * 16;
                af[mt][0] = __float_as_uint(As[(m + g) * APD + k0 + t]);
                af[mt][1] = __float_as_uint(As[(m + g + 8) * APD + k0 + t]);
                af[mt][2] = __float_as_uint(As[(m + g) * APD + k0 + t + 4]);
                af[mt][3] = __float_as_uint(As[(m + g + 8) * APD + k0 + t + 4]);
            }
            uint32_t bf[2][2];
#pragma unroll
            for (int nt = 0; nt < 2; nt++) {
                int n = wn * 16 + nt * 8;
                bf[nt][0] = __float_as_uint(Bs[(kg + t) * BPD + n + g]);
                bf[nt][1] = __float_as_uint(Bs[(kg + t + 4) * BPD + n + g]);
            }
#pragma unroll
            for (int mt = 0; mt < 4; mt++)
#pragma unroll
                for (int nt = 0; nt < 2; nt++)
                    mma_tf32(d[mt][nt][0], d[mt][nt][1], d[mt][nt][2], d[mt][nt][3],
                             af[mt][0], af[mt][1], af[mt][2], af[mt][3],
                             bf[nt][0], bf[nt][1]);
        }
    }

    // epilogue: bias, store, column stats
    // d0 -> (g, 2t), d1 -> (g, 2t+1), d2 -> (g+8, 2t), d3 -> (g+8, 2t+1)
#pragma unroll
    for (int nt = 0; nt < 2; nt++) {
        int cl = wn * 16 + nt * 8 + 2 * t;    // col local to this CTA's 64-wide slab
        int c = col0 + cl;                     // global col
        float b0 = __ldg(&bias[c]), b1 = __ldg(&bias[c + 1]);
        float ps0 = 0.f, ps1 = 0.f, pq0 = 0.f, pq1 = 0.f;
#pragma unroll
        for (int mt = 0; mt < 4; mt++) {
            int gr0 = row0 + wm * 64 + mt * 16 + g;
            int gr1 = gr0 + 8;
            if (gr0 < N) {
                float z0 = d[mt][nt][0] + b0;
                float z1 = d[mt][nt][1] + b1;
                ps0 += z0; pq0 += z0 * z0;
                ps1 += z1; pq1 += z1 * z1;
                *(float2*)&Zout[(size_t)gr0 * HIDDEN + c] = make_float2(z0, z1);
            }
            if (gr1 < N) {
                float z2 = d[mt][nt][2] + b0;
                float z3 = d[mt][nt][3] + b1;
                ps0 += z2; pq0 += z2 * z2;
                ps1 += z3; pq1 += z3 * z3;
                *(float2*)&Zout[(size_t)gr1 * HIDDEN + c] = make_float2(z2, z3);
            }
        }
        atomicAdd(&ssum[cl], ps0);
        atomicAdd(&ssq[cl], pq0);
        atomicAdd(&ssum[cl + 1], ps1);
        atomicAdd(&ssq[cl + 1], pq1);
    }
    __syncthreads();
    if (tid < NTILE) {
        atomicAdd(&sumOut[col0 + tid], (double)ssum[tid]);
        atomicAdd(&sqOut[col0 + tid], (double)ssq[tid]);
    }
}

// ---------------- layer-2 scatter: agg2[dst] += relu(bn(z2))[src], warp/edge, D=128 ----------
__global__ void scatter2_kernel(const float* __restrict__ z2,
                                const float* __restrict__ scale,
                                const float* __restrict__ shift,
                                const int* __restrict__ src,
                                const int* __restrict__ dst,
                                float* __restrict__ agg2, int E) {
    __shared__ float sc[HIDDEN], sh[HIDDEN];
    int tid = threadIdx.x;
    if (tid < HIDDEN) { sc[tid] = scale[tid]; sh[tid] = shift[tid]; }
    __syncthreads();
    int warp = tid >> 5, lane = tid & 31;
    int e = blockIdx.x * 8 + warp;
    if (e >= E) return;
    int s = __ldg(&src[e]);
    int d = __ldg(&dst[e]);
    int o = lane * 4;
    float4 z = *(const float4*)&z2[(size_t)s * HIDDEN + o];
    float4 v;
    v.x = fmaxf(0.f, sc[o + 0] * z.x + sh[o + 0]);
    v.y = fmaxf(0.f, sc[o + 1] * z.y + sh[o + 1]);
    v.z = fmaxf(0.f, sc[o + 2] * z.z + sh[o + 2]);
    v.w = fmaxf(0.f, sc[o + 3] * z.w + sh[o + 3]);
    red_add_v4(&agg2[(size_t)d * HIDDEN + o], v);
}

// ---------------- final: logits = relu(bn(z4)) @ wf + bf -> log_softmax, warp/row ----------
__global__ void final_kernel(const float* __restrict__ z4,
                             const float* __restrict__ scale,
                             const float* __restrict__ shift,
                             const float* __restrict__ wf,
                             const float* __restrict__ bf,
                             float* __restrict__ out, int N) {
    __shared__ float wfs[HIDDEN * N_CLASS];
    __shared__ float sc[HIDDEN], sh[HIDDEN];
    int tid = threadIdx.x;
    for (int i = tid; i < HIDDEN * N_CLASS; i += 256) wfs[i] = wf[i];
    if (tid < HIDDEN) { sc[tid] = scale[tid]; sh[tid] = shift[tid]; }
    __syncthreads();
    int warp = tid >> 5, lane = tid & 31;
    int n = blockIdx.x * 8 + warp;
    if (n >= N) return;
    int o = lane * 4;
    float4 z = *(const float4*)&z4[(size_t)n * HIDDEN + o];
    float y[4];
    y[0] = fmaxf(0.f, sc[o + 0] * z.x + sh[o + 0]);
    y[1] = fmaxf(0.f, sc[o + 1] * z.y + sh[o + 1]);
    y[2] = fmaxf(0.f, sc[o + 2] * z.z + sh[o + 2]);
    y[3] = fmaxf(0.f, sc[o + 3] * z.w + sh[o + 3]);
    float acc[N_CLASS];
#pragma unroll
    for (int j = 0; j < N_CLASS; j++) acc[j] = 0.f;
#pragma unroll
    for (int i = 0; i < 4; i++) {
        const float* wr = &wfs[(o + i) * N_CLASS];
#pragma unroll
        for (int j = 0; j < N_CLASS; j++) acc[j] = fmaf(y[i], wr[j], acc[j]);
    }
#pragma unroll
    for (int off = 16; off > 0; off >>= 1)
#pragma unroll
        for (int j = 0; j < N_CLASS; j++)
            acc[j] += __shfl_xor_sync(0xFFFFFFFFu, acc[j], off);
    if (lane == 0) {
        float l[N_CLASS];
        float m = -1e30f;
#pragma unroll
        for (int j = 0; j < N_CLASS; j++) {
            l[j] = acc[j] + __ldg(&bf[j]);
            m = fmaxf(m, l[j]);
        }
        float s = 0.f;
#pragma unroll
        for (int j = 0; j < N_CLASS; j++) s += __expf(l[j] - m);
        float lg = m + logf(s);
#pragma unroll
        for (int j = 0; j < N_CLASS; j++) out[(size_t)n * N_CLASS + j] = l[j] - lg;
    }
}

// ---------------- host launch ----------------
extern "C" void kernel_launch(void* const* d_in, const int* in_sizes, int n_in,
                              void* d_out, int out_size) {
    const float* x   = (const float*)d_in[0];
    const float* w11 = (const float*)d_in[2];
    const float* b11 = (const float*)d_in[3];
    const float* g11 = (const float*)d_in[4];
    const float* t11 = (const float*)d_in[5];
    const float* w12 = (const float*)d_in[6];
    const float* b12 = (const float*)d_in[7];
    const float* g12 = (const float*)d_in[8];
    const float* t12 = (const float*)d_in[9];
    const float* w21 = (const float*)d_in[10];
    const float* b21 = (const float*)d_in[11];
    const float* g21 = (const float*)d_in[12];
    const float* t21 = (const float*)d_in[13];
    const float* w22 = (const float*)d_in[14];
    const float* b22 = (const float*)d_in[15];
    const float* g22 = (const float*)d_in[16];
    const float* t22 = (const float*)d_in[17];
    const float* wf  = (const float*)d_in[18];
    const float* bf  = (const float*)d_in[19];
    const int*   ei  = (const int*)d_in[20];   // int32 on device (harness dtype set)

    int N = in_sizes[0] / N_CLASS;       // 100000
    int E = in_sizes[20] / 2;            // 1600000
    const int* src = ei;
    const int* dst = ei + E;

    float *agg1, *agg2, *buf1, *buf2, *scale, *shift;
    double *bnsum, *bnsq;
    cudaGetSymbolAddress((void**)&agg1, g_agg1);
    cudaGetSymbolAddress((void**)&agg2, g_agg2);
    cudaGetSymbolAddress((void**)&buf1, g_buf1);
    cudaGetSymbolAddress((void**)&buf2, g_buf2);
    cudaGetSymbolAddress((void**)&scale, g_scale);
    cudaGetSymbolAddress((void**)&shift, g_shift);
    cudaGetSymbolAddress((void**)&bnsum, g_bnsum);
    cudaGetSymbolAddress((void**)&bnsq, g_bnsq);

    const size_t SMEM_GEMM = (size_t)(HIDDEN * BPD + MTILE * APD + 2 * NTILE) * sizeof(float);
    cudaFuncSetAttribute(gemmB<0>, cudaFuncAttributeMaxDynamicSharedMemorySize, (int)SMEM_GEMM);
    cudaFuncSetAttribute(gemmB<1>, cudaFuncAttributeMaxDynamicSharedMemorySize, (int)SMEM_GEMM);

    cudaMemsetAsync(agg1, 0, (size_t)N * N_CLASS * sizeof(float), 0);
    cudaMemsetAsync(agg2, 0, (size_t)N * HIDDEN * sizeof(float), 0);
    cudaMemsetAsync(bnsum, 0, 4 * HIDDEN * sizeof(double), 0);
    cudaMemsetAsync(bnsq, 0, 4 * HIDDEN * sizeof(double), 0);

    double invN = 1.0 / (double)N;
    dim3 gGrid((N + MTILE - 1) / MTILE, HIDDEN / NTILE);   // (782, 2)

    // layer 1
    scatter1_kernel<<<(E + 255) / 256, 256>>>(x, src, dst, agg1, E);
    gemm1_kernel<<<(N + 7) / 8, dim3(HIDDEN, 8)>>>(x, agg1, w11, b11, buf1,
                                                   bnsum + 0 * HIDDEN, bnsq + 0 * HIDDEN, N);
    bn_finalize<<<1, HIDDEN>>>(bnsum + 0 * HIDDEN, bnsq + 0 * HIDDEN, g11, t11,
                               scale + 0 * HIDDEN, shift + 0 * HIDDEN, invN);
    gemmB<0><<<gGrid, 256, SMEM_GEMM>>>(buf1, nullptr, w12, b12,
                                        scale + 0 * HIDDEN, shift + 0 * HIDDEN,
                                        buf2, bnsum + 1 * HIDDEN, bnsq + 1 * HIDDEN, N);
    bn_finalize<<<1, HIDDEN>>>(bnsum + 1 * HIDDEN, bnsq + 1 * HIDDEN, g12, t12,
                               scale + 1 * HIDDEN, shift + 1 * HIDDEN, invN);

    // layer 2 (h_out1 = relu(bn1(z2)) recomputed on the fly; never materialized)
    scatter2_kernel<<<(E + 7) / 8, 256>>>(buf2, scale + 1 * HIDDEN, shift + 1 * HIDDEN,
                                          src, dst, agg2, E);
    gemmB<1><<<gGrid, 256, SMEM_GEMM>>>(buf2, agg2, w21, b21,
                                        scale + 1 * HIDDEN, shift + 1 * HIDDEN,
                                        buf1, bnsum + 2 * HIDDEN, bnsq + 2 * HIDDEN, N);
    bn_finalize<<<1, HIDDEN>>>(bnsum + 2 * HIDDEN, bnsq + 2 * HIDDEN, g21, t21,
                               scale + 2 * HIDDEN, shift + 2 * HIDDEN, invN);
    gemmB<0><<<gGrid, 256, SMEM_GEMM>>>(buf1, nullptr, w22, b22,
                                        scale + 2 * HIDDEN, shift + 2 * HIDDEN,
                                        buf2, bnsum + 3 * HIDDEN, bnsq + 3 * HIDDEN, N);
    bn_finalize<<<1, HIDDEN>>>(bnsum + 3 * HIDDEN, bnsq + 3 * HIDDEN, g22, t22,
                               scale + 3 * HIDDEN, shift + 3 * HIDDEN, invN);

    // readout
    final_kernel<<<(N + 7) / 8, 256>>>(buf2, scale + 3 * HIDDEN, shift + 3 * HIDDEN,
                                       wf, bf, (float*)d_out, N);
}